// round 1
// baseline (speedup 1.0000x reference)
#include <cuda_runtime.h>

// DeepKoopman: B=1024,S=512,D=32,L=64,H=64,P=256
// Outputs concatenated: x_rec[B,S,D], x_dyn[B,S,D], x_pred[B,P,D], z[B,S,L], z_dyn[B,S,L]

namespace {
constexpr int Bn = 1024, Sn = 512, Dn = 32, Ln = 64, Hn = 64, Pn = 256;
constexpr int BS = Bn * Sn;                               // 524288
constexpr long OFF_XREC  = 0;
constexpr long OFF_XDYN  = (long)BS * Dn;                 // 16777216
constexpr long OFF_XPRED = OFF_XDYN * 2;                  // 33554432
constexpr long OFF_Z     = OFF_XPRED + (long)Bn * Pn * Dn;// 41943040
constexpr long OFF_ZDYN  = OFF_Z + (long)BS * Ln;         // 75497472
}

// scratch (device globals; no allocation allowed)
__device__ float g_Mpow[256][Ln * Ln];            // g_Mpow[p-1] = K^p (row-major)
__device__ float g_zpred[(long)Bn * Pn * Ln];     // [B,P,L]

// ---------------------------------------------------------------------------
// Stage A1: sequential power chain in ONE block.
// Computes K^1..K^8, K^16,K^24,...,K^64, K^128, K^192  (16 sequential matmuls)
// ---------------------------------------------------------------------------
__device__ __forceinline__ void mm64_step(const float* sA, float* sB, float* gout, int tid) {
    // sC replaced by per-thread registers to keep smem at 32KB
    float r[16];
#pragma unroll
    for (int t = 0; t < 16; ++t) {
        int o = tid + t * 256;
        int row = o >> 6, c = o & 63;
        float acc = 0.f;
#pragma unroll 8
        for (int k = 0; k < 64; ++k) acc += sA[row * 64 + k] * sB[k * 64 + c];
        r[t] = acc;
    }
    __syncthreads();
#pragma unroll
    for (int t = 0; t < 16; ++t) {
        int o = tid + t * 256;
        sB[o] = r[t];
        gout[o] = r[t];
    }
    __syncthreads();
}

__global__ void __launch_bounds__(256) kA1(const float* __restrict__ Kw) {
    __shared__ float sA[4096], sB[4096];
    int tid = threadIdx.x;
#pragma unroll
    for (int t = 0; t < 16; ++t) {
        int o = tid + t * 256;
        float v = Kw[o];
        sA[o] = v; sB[o] = v;
        g_Mpow[0][o] = v;
    }
    __syncthreads();
    for (int p = 2; p <= 8; ++p) mm64_step(sA, sB, g_Mpow[p - 1], tid);   // sB = K^8
#pragma unroll
    for (int t = 0; t < 16; ++t) { int o = tid + t * 256; sA[o] = sB[o]; }
    __syncthreads();
    for (int q = 2; q <= 8; ++q) mm64_step(sA, sB, g_Mpow[8 * q - 1], tid); // sB = K^64
#pragma unroll
    for (int t = 0; t < 16; ++t) { int o = tid + t * 256; sA[o] = sB[o]; }
    __syncthreads();
    mm64_step(sA, sB, g_Mpow[127], tid);  // K^128
    mm64_step(sA, sB, g_Mpow[191], tid);  // K^192 = K^64 * K^128
}

// ---------------------------------------------------------------------------
// Stage A2a: K^(8q+r) = K^(8q) * K^r, q=1..7, r=1..7  (fills all p in 1..64)
// Stage A2b: K^(64t+m) = K^(64t) * K^m, t=1..3, m=1..64 (skip p=128,192: done in A1)
// ---------------------------------------------------------------------------
__device__ __forceinline__ void mm64_gg(const float* __restrict__ ga, const float* __restrict__ gb,
                                        float* __restrict__ gd, float* sA, float* sB, int tid) {
#pragma unroll
    for (int t = 0; t < 16; ++t) {
        int o = tid + t * 256;
        sA[o] = ga[o]; sB[o] = gb[o];
    }
    __syncthreads();
#pragma unroll
    for (int t = 0; t < 16; ++t) {
        int o = tid + t * 256;
        int row = o >> 6, c = o & 63;
        float acc = 0.f;
#pragma unroll 8
        for (int k = 0; k < 64; ++k) acc += sA[row * 64 + k] * sB[k * 64 + c];
        gd[o] = acc;
    }
}

__global__ void __launch_bounds__(256) kA2a() {
    int q = blockIdx.x / 7 + 1, r = blockIdx.x % 7 + 1;
    __shared__ float sA[4096], sB[4096];
    mm64_gg(g_Mpow[8 * q - 1], g_Mpow[r - 1], g_Mpow[8 * q + r - 1], sA, sB, threadIdx.x);
}

__global__ void __launch_bounds__(256) kA2b() {
    int t = blockIdx.x / 64 + 1, m = blockIdx.x % 64 + 1;
    if (m == 64 && t <= 2) return;  // p=128,192 already produced by A1 (avoid RAW race)
    __shared__ float sA[4096], sB[4096];
    mm64_gg(g_Mpow[64 * t - 1], g_Mpow[m - 1], g_Mpow[64 * t + m - 1], sA, sB, threadIdx.x);
}

// ---------------------------------------------------------------------------
// Encoder: x -> z (write), z -> z_dyn (write).  One thread per (b,s) row.
// ---------------------------------------------------------------------------
__global__ void __launch_bounds__(256) kEnc(
    const float* __restrict__ x,
    const float* __restrict__ ew1, const float* __restrict__ eb1,
    const float* __restrict__ ew2, const float* __restrict__ eb2,
    const float* __restrict__ Kw,
    float* __restrict__ out)
{
    __shared__ float s_w1[Hn * Dn];   // [j][i], row-major as given
    __shared__ float s_w2t[Hn * Ln];  // [j][l] = ew2[l*H + j] (transposed)
    __shared__ float s_K[Ln * Ln];    // [l][i], row-major as given
    __shared__ float s_b1[Hn];
    __shared__ float s_b2[Ln];
    int tid = threadIdx.x;
    for (int i = tid; i < Hn * Dn; i += 256) s_w1[i] = ew1[i];
    for (int i = tid; i < Hn * Ln; i += 256) {
        int j = i >> 6, l = i & 63;
        s_w2t[i] = ew2[l * Hn + j];
    }
    for (int i = tid; i < Ln * Ln; i += 256) s_K[i] = Kw[i];
    if (tid < Hn) s_b1[tid] = eb1[tid];
    if (tid < Ln) s_b2[tid] = eb2[tid];
    __syncthreads();

    long row = (long)blockIdx.x * 256 + tid;

    float xv[Dn];
    const float4* xp = reinterpret_cast<const float4*>(x + row * Dn);
#pragma unroll
    for (int i4 = 0; i4 < Dn / 4; ++i4) {
        float4 v = xp[i4];
        xv[i4 * 4] = v.x; xv[i4 * 4 + 1] = v.y; xv[i4 * 4 + 2] = v.z; xv[i4 * 4 + 3] = v.w;
    }

    float z[Ln];
#pragma unroll
    for (int l = 0; l < Ln; ++l) z[l] = s_b2[l];

    // z = relu(x@W1^T + b1) @ W2^T + b2   (stream over hidden j)
#pragma unroll 4
    for (int j = 0; j < Hn; ++j) {
        float acc = s_b1[j];
        const float4* w1r = reinterpret_cast<const float4*>(s_w1 + j * Dn);
#pragma unroll
        for (int i4 = 0; i4 < Dn / 4; ++i4) {
            float4 w = w1r[i4];
            acc += xv[i4 * 4] * w.x + xv[i4 * 4 + 1] * w.y + xv[i4 * 4 + 2] * w.z + xv[i4 * 4 + 3] * w.w;
        }
        float hj = fmaxf(acc, 0.f);
        const float4* w2r = reinterpret_cast<const float4*>(s_w2t + j * Ln);
#pragma unroll
        for (int l4 = 0; l4 < Ln / 4; ++l4) {
            float4 w = w2r[l4];
            z[l4 * 4]     += hj * w.x;
            z[l4 * 4 + 1] += hj * w.y;
            z[l4 * 4 + 2] += hj * w.z;
            z[l4 * 4 + 3] += hj * w.w;
        }
    }

    float4* zo = reinterpret_cast<float4*>(out + OFF_Z + row * Ln);
#pragma unroll
    for (int l4 = 0; l4 < 16; ++l4)
        zo[l4] = make_float4(z[l4 * 4], z[l4 * 4 + 1], z[l4 * 4 + 2], z[l4 * 4 + 3]);

    // z_dyn[l] = sum_i z[i] * K[l][i]
    float4* zdo = reinterpret_cast<float4*>(out + OFF_ZDYN + row * Ln);
#pragma unroll 1
    for (int l4 = 0; l4 < 16; ++l4) {
        float tacc[4];
#pragma unroll
        for (int u = 0; u < 4; ++u) {
            int l = l4 * 4 + u;
            float acc = 0.f;
            const float4* kr = reinterpret_cast<const float4*>(s_K + l * Ln);
#pragma unroll
            for (int i4 = 0; i4 < 16; ++i4) {
                float4 w = kr[i4];
                acc += z[i4 * 4] * w.x + z[i4 * 4 + 1] * w.y + z[i4 * 4 + 2] * w.z + z[i4 * 4 + 3] * w.w;
            }
            tacc[u] = acc;
        }
        zdo[l4] = make_float4(tacc[0], tacc[1], tacc[2], tacc[3]);
    }
}

// ---------------------------------------------------------------------------
// Pred rollout (parallelized): z_pred[b,p,l] = sum_i z_last[b,i] * (K^(p+1))[l][i]
// One block per p; 4 b's per thread.
// ---------------------------------------------------------------------------
__global__ void __launch_bounds__(256) kPredZ(const float* __restrict__ zfull) {
    int p = blockIdx.x;  // 0..255
    __shared__ float sM[Ln * Ln];
    int tid = threadIdx.x;
#pragma unroll
    for (int t = 0; t < 16; ++t) sM[tid + t * 256] = g_Mpow[p][tid + t * 256];
    __syncthreads();

    for (int bb = 0; bb < 4; ++bb) {
        int b = bb * 256 + tid;
        const float4* z0p = reinterpret_cast<const float4*>(zfull + ((long)b * Sn + (Sn - 1)) * Ln);
        float z0[Ln];
#pragma unroll
        for (int l4 = 0; l4 < 16; ++l4) {
            float4 v = z0p[l4];
            z0[l4 * 4] = v.x; z0[l4 * 4 + 1] = v.y; z0[l4 * 4 + 2] = v.z; z0[l4 * 4 + 3] = v.w;
        }
        float4* zo = reinterpret_cast<float4*>(g_zpred + ((long)b * Pn + p) * Ln);
#pragma unroll 1
        for (int l4 = 0; l4 < 16; ++l4) {
            float tacc[4];
#pragma unroll
            for (int u = 0; u < 4; ++u) {
                int l = l4 * 4 + u;
                float acc = 0.f;
                const float4* mr = reinterpret_cast<const float4*>(sM + l * Ln);
#pragma unroll
                for (int i4 = 0; i4 < 16; ++i4) {
                    float4 w = mr[i4];
                    acc += z0[i4 * 4] * w.x + z0[i4 * 4 + 1] * w.y + z0[i4 * 4 + 2] * w.z + z0[i4 * 4 + 3] * w.w;
                }
                tacc[u] = acc;
            }
            zo[l4] = make_float4(tacc[0], tacc[1], tacc[2], tacc[3]);
        }
    }
}

// ---------------------------------------------------------------------------
// Decoder: xout = relu(zin@W1^T + b1) @ W2^T + b2.  One thread per row.
// zin == nullptr means "read g_zpred".
// ---------------------------------------------------------------------------
__global__ void __launch_bounds__(256) kDec(
    const float* __restrict__ zin, float* __restrict__ xout,
    const float* __restrict__ dw1, const float* __restrict__ db1,
    const float* __restrict__ dw2, const float* __restrict__ db2)
{
    __shared__ float s_w1[Hn * Ln];   // [j][l] row-major as given
    __shared__ float s_w2t[Hn * Dn];  // [j][d] = dw2[d*H + j] (transposed)
    __shared__ float s_b1[Hn], s_b2[Dn];
    int tid = threadIdx.x;
    for (int i = tid; i < Hn * Ln; i += 256) s_w1[i] = dw1[i];
    for (int i = tid; i < Hn * Dn; i += 256) {
        int j = i >> 5, d = i & 31;
        s_w2t[i] = dw2[d * Hn + j];
    }
    if (tid < Hn) s_b1[tid] = db1[tid];
    if (tid < Dn) s_b2[tid] = db2[tid];
    __syncthreads();

    const float* zbase = zin ? zin : g_zpred;
    long row = (long)blockIdx.x * 256 + tid;

    float zv[Ln];
    const float4* zp = reinterpret_cast<const float4*>(zbase + row * Ln);
#pragma unroll
    for (int l4 = 0; l4 < 16; ++l4) {
        float4 v = zp[l4];
        zv[l4 * 4] = v.x; zv[l4 * 4 + 1] = v.y; zv[l4 * 4 + 2] = v.z; zv[l4 * 4 + 3] = v.w;
    }

    float xa[Dn];
#pragma unroll
    for (int d = 0; d < Dn; ++d) xa[d] = s_b2[d];

#pragma unroll 4
    for (int j = 0; j < Hn; ++j) {
        float acc = s_b1[j];
        const float4* w1r = reinterpret_cast<const float4*>(s_w1 + j * Ln);
#pragma unroll
        for (int l4 = 0; l4 < 16; ++l4) {
            float4 w = w1r[l4];
            acc += zv[l4 * 4] * w.x + zv[l4 * 4 + 1] * w.y + zv[l4 * 4 + 2] * w.z + zv[l4 * 4 + 3] * w.w;
        }
        float hj = fmaxf(acc, 0.f);
        const float4* w2r = reinterpret_cast<const float4*>(s_w2t + j * Dn);
#pragma unroll
        for (int d4 = 0; d4 < Dn / 4; ++d4) {
            float4 w = w2r[d4];
            xa[d4 * 4]     += hj * w.x;
            xa[d4 * 4 + 1] += hj * w.y;
            xa[d4 * 4 + 2] += hj * w.z;
            xa[d4 * 4 + 3] += hj * w.w;
        }
    }

    float4* xo = reinterpret_cast<float4*>(xout + row * Dn);
#pragma unroll
    for (int d4 = 0; d4 < Dn / 4; ++d4)
        xo[d4] = make_float4(xa[d4 * 4], xa[d4 * 4 + 1], xa[d4 * 4 + 2], xa[d4 * 4 + 3]);
}

// ---------------------------------------------------------------------------
extern "C" void kernel_launch(void* const* d_in, const int* in_sizes, int n_in,
                              void* d_out, int out_size) {
    const float* x   = (const float*)d_in[0];
    const float* ew1 = (const float*)d_in[1];
    const float* eb1 = (const float*)d_in[2];
    const float* ew2 = (const float*)d_in[3];
    const float* eb2 = (const float*)d_in[4];
    const float* dw1 = (const float*)d_in[5];
    const float* db1 = (const float*)d_in[6];
    const float* dw2 = (const float*)d_in[7];
    const float* db2 = (const float*)d_in[8];
    const float* Kw  = (const float*)d_in[9];
    float* out = (float*)d_out;

    // Koopman power table: 16 sequential 64x64 matmuls, then parallel fill
    kA1<<<1, 256>>>(Kw);
    kA2a<<<49, 256>>>();
    kA2b<<<192, 256>>>();

    // Encoder: z and z_dyn
    kEnc<<<BS / 256, 256>>>(x, ew1, eb1, ew2, eb2, Kw, out);

    // Parallel rollout z_pred = z_last @ (K^T)^p
    kPredZ<<<Pn, 256>>>(out + OFF_Z);

    // Decoders
    kDec<<<BS / 256, 256>>>(out + OFF_Z,    out + OFF_XREC,  dw1, db1, dw2, db2);
    kDec<<<BS / 256, 256>>>(out + OFF_ZDYN, out + OFF_XDYN,  dw1, db1, dw2, db2);
    kDec<<<(Bn * Pn) / 256, 256>>>(nullptr, out + OFF_XPRED, dw1, db1, dw2, db2);
}